// round 7
// baseline (speedup 1.0000x reference)
#include <cuda_runtime.h>
#include <cuda_bf16.h>
#include <cstdint>

#define BATCH 8
#define SEQ   2048
#define DIM   128
#define INV_TEMP 0.08838834764831843f
// INV_TEMP * log2(e), folded for exp2f
#define EXP2_SCALE (0.08838834764831843f * 1.44269504088896340f)

typedef unsigned long long ull;

// ---------------- device scratch ----------------
__device__ float g_inv_rs[BATCH * SEQ];
__device__ __align__(16) __nv_bfloat16 g_qhi[BATCH * SEQ * DIM];
__device__ __align__(16) __nv_bfloat16 g_qlo[BATCH * SEQ * DIM];
__device__ __align__(16) __nv_bfloat16 g_vhi[BATCH * SEQ * DIM];
__device__ __align__(16) __nv_bfloat16 g_vlo[BATCH * SEQ * DIM];

// ---------------- cp.async ----------------
__device__ __forceinline__ void cp_async16(uint32_t smem_dst, const void* gsrc) {
    asm volatile("cp.async.ca.shared.global [%0], [%1], 16;\n"
                 :: "r"(smem_dst), "l"(gsrc));
}
#define CP_COMMIT() asm volatile("cp.async.commit_group;\n" ::: "memory")
#define CP_WAIT0()  asm volatile("cp.async.wait_group 0;\n" ::: "memory")
#define CP_WAIT1()  asm volatile("cp.async.wait_group 1;\n" ::: "memory")

__device__ __forceinline__ uint32_t smem_u32(const void* p) {
    uint32_t a;
    asm("{ .reg .u64 t; cvta.to.shared.u64 t, %1; cvt.u32.u64 %0, t; }"
        : "=r"(a) : "l"(p));
    return a;
}

// ---------------- mma / ldmatrix ----------------
__device__ __forceinline__ void ldm4(unsigned* r, uint32_t addr) {
    asm volatile("ldmatrix.sync.aligned.m8n8.x4.shared.b16 {%0,%1,%2,%3}, [%4];"
                 : "=r"(r[0]), "=r"(r[1]), "=r"(r[2]), "=r"(r[3]) : "r"(addr));
}
__device__ __forceinline__ void ldm4t(unsigned* r, uint32_t addr) {
    asm volatile("ldmatrix.sync.aligned.m8n8.x4.trans.shared.b16 {%0,%1,%2,%3}, [%4];"
                 : "=r"(r[0]), "=r"(r[1]), "=r"(r[2]), "=r"(r[3]) : "r"(addr));
}
__device__ __forceinline__ void mma16816(float* d, const unsigned* a,
                                         const unsigned* b) {
    asm volatile(
        "mma.sync.aligned.m16n8k16.row.col.f32.bf16.bf16.f32 "
        "{%0,%1,%2,%3}, {%4,%5,%6,%7}, {%8,%9}, {%0,%1,%2,%3};"
        : "+f"(d[0]), "+f"(d[1]), "+f"(d[2]), "+f"(d[3])
        : "r"(a[0]), "r"(a[1]), "r"(a[2]), "r"(a[3]), "r"(b[0]), "r"(b[1]));
}

// =====================================================================
// split kernel: q,v -> bf16 hi/lo
// =====================================================================
__global__ void __launch_bounds__(256)
split_kernel(const float* __restrict__ q, const float* __restrict__ v) {
    int i = (blockIdx.x * 256 + threadIdx.x) * 4;
    float4 fq = *(const float4*)(q + i);
    float4 fv = *(const float4*)(v + i);
    float xq[4] = {fq.x, fq.y, fq.z, fq.w};
    float xv[4] = {fv.x, fv.y, fv.z, fv.w};
    __nv_bfloat16 qh[4], ql[4], vh[4], vl[4];
#pragma unroll
    for (int j = 0; j < 4; ++j) {
        qh[j] = __float2bfloat16(xq[j]);
        ql[j] = __float2bfloat16(xq[j] - __bfloat162float(qh[j]));
        vh[j] = __float2bfloat16(xv[j]);
        vl[j] = __float2bfloat16(xv[j] - __bfloat162float(vh[j]));
    }
    *(ull*)(g_qhi + i) = *(ull*)qh;
    *(ull*)(g_qlo + i) = *(ull*)ql;
    *(ull*)(g_vhi + i) = *(ull*)vh;
    *(ull*)(g_vlo + i) = *(ull*)vl;
}

// =====================================================================
// Pass 1 (mma.sync bf16 split, term-major ordering)
// =====================================================================
#define PITCH 272
#define TILE_B (128 * PITCH)
#define OFF_QLO   0
#define OFF_VBUF(x) (TILE_B + (x) * (2 * TILE_B))
#define OFF_RS    (TILE_B + 4 * TILE_B)
#define P1_SMEM   (OFF_RS + 128 * 2 * 4)

__device__ __forceinline__ void stage_tile(uint32_t dst,
                                           const __nv_bfloat16* src, int t) {
#pragma unroll
    for (int it = 0; it < 8; ++it) {
        int id = it * 256 + t;
        int r = id >> 4, c = id & 15;
        cp_async16(dst + r * PITCH + c * 16, src + r * 128 + c * 8);
    }
}

__global__ void __launch_bounds__(256, 1)
pass1_kernel(float* __restrict__ u) {
    extern __shared__ char sm[];
    const uint32_t smb = smem_u32(sm);
    float* rsbuf = (float*)(sm + OFF_RS);

    const int b  = blockIdx.y;
    const int i0 = blockIdx.x * 128;
    const int t  = threadIdx.x;
    const int w  = t >> 5;
    const int l  = t & 31;
    const int wm = w & 3;
    const int wn = w >> 2;

    const __nv_bfloat16* qhg = g_qhi + ((size_t)b * SEQ + i0) * DIM;
    const __nv_bfloat16* qlg = g_qlo + ((size_t)b * SEQ + i0) * DIM;
    const __nv_bfloat16* vhg = g_vhi + (size_t)b * SEQ * DIM;
    const __nv_bfloat16* vlg = g_vlo + (size_t)b * SEQ * DIM;

    const int rA = (l & 7) + ((l >> 3) & 1) * 8;
    const int cA = (l >> 4) * 8;
    const int rB = (l & 7) + (l >> 4) * 8;
    const int cB = ((l >> 3) & 1) * 8;

    stage_tile(smb + OFF_VBUF(0), qhg, t);
    stage_tile(smb + OFF_QLO,     qlg, t);
    CP_COMMIT();
    CP_WAIT0();
    __syncthreads();

    unsigned qh[2][8][4];
#pragma unroll
    for (int f = 0; f < 2; ++f)
#pragma unroll
        for (int k8 = 0; k8 < 8; ++k8) {
            uint32_t addr = smb + OFF_VBUF(0) +
                (wm * 32 + f * 16 + rA) * PITCH + (k8 * 16 + cA) * 2;
            ldm4(qh[f][k8], addr);
        }
    __syncthreads();

    uint32_t qloA[2];
#pragma unroll
    for (int f = 0; f < 2; ++f)
        qloA[f] = smb + OFF_QLO + (wm * 32 + f * 16 + rA) * PITCH + cA * 2;

    uint32_t bRow[4];
#pragma unroll
    for (int p = 0; p < 4; ++p)
        bRow[p] = (wn * 64 + p * 16 + rB) * PITCH + cB * 2;

    stage_tile(smb + OFF_VBUF(0),          vhg, t);
    stage_tile(smb + OFF_VBUF(0) + TILE_B, vlg, t);
    CP_COMMIT();
    stage_tile(smb + OFF_VBUF(1),          vhg + 128 * DIM, t);
    stage_tile(smb + OFF_VBUF(1) + TILE_B, vlg + 128 * DIM, t);
    CP_COMMIT();

    float* up[2];
#pragma unroll
    for (int f = 0; f < 2; ++f)
        up[f] = u + ((size_t)(b * SEQ + i0 + wm * 32 + f * 16 + (l >> 2))) * SEQ
                  + wn * 64 + (l & 3) * 2;

    float rs[2][2] = {{0.f, 0.f}, {0.f, 0.f}};
    const int NCHUNK = SEQ / 128;

    for (int c = 0; c < NCHUNK; ++c) {
        CP_WAIT1();
        __syncthreads();

        const uint32_t vh = smb + OFF_VBUF(c & 1);
        const uint32_t vl = vh + TILE_B;

        float acc[2][8][4];
#pragma unroll
        for (int f = 0; f < 2; ++f)
#pragma unroll
            for (int n = 0; n < 8; ++n)
#pragma unroll
                for (int x = 0; x < 4; ++x) acc[f][n][x] = 0.0f;

#pragma unroll
        for (int k8 = 0; k8 < 8; ++k8) {
            unsigned bh[4][4];
#pragma unroll
            for (int p = 0; p < 4; ++p)
                ldm4(bh[p], vh + bRow[p] + k8 * 32);
            unsigned al[2][4];
            ldm4(al[0], qloA[0] + k8 * 32);
            ldm4(al[1], qloA[1] + k8 * 32);

            // term 1: Qhi . Vhi  (16 mma, all-distinct accumulators)
#pragma unroll
            for (int p = 0; p < 4; ++p)
#pragma unroll
                for (int h = 0; h < 2; ++h) {
                    const unsigned* bb = &bh[p][2 * h];
                    int n = 2 * p + h;
                    mma16816(acc[0][n], qh[0][k8], bb);
                    mma16816(acc[1][n], qh[1][k8], bb);
                }
            // term 2: Qlo . Vhi
#pragma unroll
            for (int p = 0; p < 4; ++p)
#pragma unroll
                for (int h = 0; h < 2; ++h) {
                    const unsigned* bb = &bh[p][2 * h];
                    int n = 2 * p + h;
                    mma16816(acc[0][n], al[0], bb);
                    mma16816(acc[1][n], al[1], bb);
                }
            // load Vlo frags
            unsigned bl[4][4];
#pragma unroll
            for (int p = 0; p < 4; ++p)
                ldm4(bl[p], vl + bRow[p] + k8 * 32);
            // term 3: Qhi . Vlo
#pragma unroll
            for (int p = 0; p < 4; ++p)
#pragma unroll
                for (int h = 0; h < 2; ++h) {
                    const unsigned* bb = &bl[p][2 * h];
                    int n = 2 * p + h;
                    mma16816(acc[0][n], qh[0][k8], bb);
                    mma16816(acc[1][n], qh[1][k8], bb);
                }
        }

        __syncthreads();

        if (c + 2 < NCHUNK) {
            const uint32_t nb = smb + OFF_VBUF(c & 1);
            stage_tile(nb,          vhg + (size_t)(c + 2) * 128 * DIM, t);
            stage_tile(nb + TILE_B, vlg + (size_t)(c + 2) * 128 * DIM, t);
        }
        CP_COMMIT();

#pragma unroll
        for (int f = 0; f < 2; ++f) {
            float* row0 = up[f] + c * 128;
            float* row1 = row0 + 8 * SEQ;
#pragma unroll
            for (int n = 0; n < 8; ++n) {
                float e0 = exp2f(acc[f][n][0] * EXP2_SCALE);
                float e1 = exp2f(acc[f][n][1] * EXP2_SCALE);
                float e2 = exp2f(acc[f][n][2] * EXP2_SCALE);
                float e3 = exp2f(acc[f][n][3] * EXP2_SCALE);
                rs[f][0] += e0 + e1;
                rs[f][1] += e2 + e3;
                *(float2*)(row0 + n * 8) = make_float2(e0, e1);
                *(float2*)(row1 + n * 8) = make_float2(e2, e3);
            }
        }
    }

#pragma unroll
    for (int f = 0; f < 2; ++f)
#pragma unroll
        for (int h = 0; h < 2; ++h) {
            rs[f][h] += __shfl_xor_sync(0xffffffffu, rs[f][h], 1);
            rs[f][h] += __shfl_xor_sync(0xffffffffu, rs[f][h], 2);
        }
    if ((l & 3) == 0) {
#pragma unroll
        for (int f = 0; f < 2; ++f)
#pragma unroll
            for (int h = 0; h < 2; ++h) {
                int row = wm * 32 + f * 16 + h * 8 + (l >> 2);
                rsbuf[row * 2 + wn] = rs[f][h];
            }
    }
    __syncthreads();
    if (t < 128)
        g_inv_rs[b * SEQ + i0 + t] = 1.0f / (rsbuf[t * 2] + rsbuf[t * 2 + 1]);
}

// =====================================================================
// Pass 2 (mma.sync, term-major ordering)
// =====================================================================
#define P2_I    64
#define UPITCH  528
#define U_BUF   (P2_I * UPITCH)
#define APITCH  272
#define ATILE   (P2_I * APITCH)
#define OFF_U(x)  ((x) * U_BUF)
#define OFF_AH(x) (2 * U_BUF + (x) * ATILE)
#define OFF_AL(x) (2 * U_BUF + 2 * ATILE + (x) * ATILE)
#define OFF_VH(x) (2 * U_BUF + 4 * ATILE + (x) * ATILE)
#define OFF_VL(x) (2 * U_BUF + 6 * ATILE + (x) * ATILE)
#define P2_SMEM   (2 * U_BUF + 8 * ATILE)

__device__ __forceinline__ void stage_u64(uint32_t dst, const float* src, int t) {
#pragma unroll
    for (int it = 0; it < 8; ++it) {
        int id = it * 256 + t;
        int r = id >> 5, c = id & 31;
        cp_async16(dst + r * UPITCH + c * 16, src + (size_t)r * SEQ + c * 4);
    }
}
__device__ __forceinline__ void stage_v64(uint32_t dst,
                                          const __nv_bfloat16* src, int t) {
#pragma unroll
    for (int it = 0; it < 4; ++it) {
        int id = it * 256 + t;
        int r = id >> 4, c = id & 15;
        cp_async16(dst + r * APITCH + c * 16, src + r * 128 + c * 8);
    }
}

__global__ void __launch_bounds__(256, 1)
pass2_kernel(float* __restrict__ attn, float* __restrict__ out) {
    extern __shared__ char sm[];
    const uint32_t smb = smem_u32(sm);

    const int b  = blockIdx.y;
    const int j0 = blockIdx.x * 128;
    const int t  = threadIdx.x;
    const int w  = t >> 5;
    const int l  = t & 31;
    const int wm = w & 3;
    const int wn = w >> 2;

    float*       ab  = attn + (size_t)b * SEQ * SEQ;
    const __nv_bfloat16* vhg = g_vhi + (size_t)b * SEQ * DIM;
    const __nv_bfloat16* vlg = g_vlo + (size_t)b * SEQ * DIM;
    const float* irs = g_inv_rs + b * SEQ;
    float*       ob  = out + (size_t)b * SEQ * DIM;

    const int rAT = (l & 7) + ((l >> 4) & 1) * 8;
    const int cAT = ((l >> 3) & 1) * 8;
    const int rBT = (l & 7) + ((l >> 3) & 1) * 8;
    const int cBT = (l >> 4) * 8;

    const int i_loc = t >> 2;
    const int jq    = t & 3;

    stage_u64(smb + OFF_U(0), ab + j0, t);
    stage_v64(smb + OFF_VH(0), vhg, t);
    stage_v64(smb + OFF_VL(0), vlg, t);
    CP_COMMIT();

    float acc[2][8][4];
#pragma unroll
    for (int f = 0; f < 2; ++f)
#pragma unroll
        for (int n = 0; n < 8; ++n)
#pragma unroll
            for (int x = 0; x < 4; ++x) acc[f][n][x] = 0.0f;

    const int NCHUNK = SEQ / P2_I;

    for (int c = 0; c < NCHUNK; ++c) {
        const int bu = c & 1;
        const int i0c = c * P2_I;

        CP_WAIT0();
        __syncthreads();

        // ---- convert: normalize u, STG attn, split to bf16 hi/lo ----
        {
            const float* urow = (const float*)(sm + OFF_U(bu) + i_loc * UPITCH);
            float* grow = ab + (size_t)(i0c + i_loc) * SEQ + j0;
            uint32_t ah = smb + OFF_AH(bu) + i_loc * APITCH;
            uint32_t al = smb + OFF_AL(bu) + i_loc * APITCH;
            const float s = __ldg(irs + i0c + i_loc);
#pragma unroll
            for (int it = 0; it < 8; ++it) {
                int j = jq * 4 + it * 16;
                float4 f4 = *(const float4*)(urow + j);
                f4.x *= s; f4.y *= s; f4.z *= s; f4.w *= s;
                *(float4*)(grow + j) = f4;
                __nv_bfloat162 h01 = __floats2bfloat162_rn(f4.x, f4.y);
                __nv_bfloat162 h23 = __floats2bfloat162_rn(f4.z, f4.w);
                __nv_bfloat162 l01 = __floats2bfloat162_rn(
                    f4.x - __bfloat162float(h01.x), f4.y - __bfloat162float(h01.y));
                __nv_bfloat162 l23 = __floats2bfloat162_rn(
                    f4.z - __bfloat162float(h23.x), f4.w - __bfloat162float(h23.y));
                unsigned hp[2] = {*(unsigned*)&h01, *(unsigned*)&h23};
                unsigned lp[2] = {*(unsigned*)&l01, *(unsigned*)&l23};
                asm volatile("st.shared.v2.b32 [%0], {%1, %2};"
                             :: "r"(ah + j * 2), "r"(hp[0]), "r"(hp[1]));
                asm volatile("st.shared.v2.b32 [%0], {%1, %2};"
                             :: "r"(al + j * 2), "r"(lp[0]), "r"(lp[1]));
            }
        }
        __syncthreads();

        if (c + 1 < NCHUNK) {
            const int nb = (c + 1) & 1;
            stage_u64(smb + OFF_U(nb), ab + (size_t)(i0c + P2_I) * SEQ + j0, t);
            stage_v64(smb + OFF_VH(nb), vhg + (size_t)(i0c + P2_I) * DIM, t);
            stage_v64(smb + OFF_VL(nb), vlg + (size_t)(i0c + P2_I) * DIM, t);
        }
        CP_COMMIT();

        // ---- MMA: term-major ----
        const uint32_t AH = smb + OFF_AH(bu);
        const uint32_t AL = smb + OFF_AL(bu);
        const uint32_t VH = smb + OFF_VH(bu);
        const uint32_t VL = smb + OFF_VL(bu);
#pragma unroll
        for (int k8 = 0; k8 < P2_I / 16; ++k8) {
            const uint32_t kro = (k8 * 16) * APITCH;
            unsigned ahf[2][4], alf[2][4];
#pragma unroll
            for (int f = 0; f < 2; ++f) {
                uint32_t coff = rAT * APITCH + (wm * 32 + f * 16 + cAT) * 2;
                ldm4t(ahf[f], AH + kro + coff);
                ldm4t(alf[f], AL + kro + coff);
            }
            unsigned bh[4][4];
#pragma unroll
            for (int p = 0; p < 4; ++p) {
                uint32_t coff = rBT * APITCH + (wn * 64 + p * 16 + cBT) * 2;
                ldm4t(bh[p], VH + kro + coff);
            }
            // term 1: Ahi . Vhi
#pragma unroll
            for (int p = 0; p < 4; ++p)
#pragma unroll
                for (int h = 0; h < 2; ++h) {
                    const unsigned* bb = &bh[p][2 * h];
                    int n = 2 * p + h;
                    mma16816(acc[0][n], ahf[0], bb);
                    mma16816(acc[1][n], ahf[1], bb);
                }
            // term 2: Alo . Vhi
#pragma unroll
            for (int p = 0; p < 4; ++p)
#pragma unroll
                for (int h = 0; h < 2; ++h) {
                    const unsigned* bb = &bh[p][2 * h];
                    int n = 2 * p + h;
                    mma16816(acc[0][n], alf[0], bb);
                    mma16816(acc[1][n], alf[1], bb);
                }
            // load Vlo frags
            unsigned bl[4][4];
#pragma unroll
            for (int p = 0; p < 4; ++p) {
                uint32_t coff = rBT * APITCH + (wn * 64 + p * 16 + cBT) * 2;
                ldm4t(bl[p], VL + kro + coff);
            }
            // term 3: Ahi . Vlo
#pragma unroll
            for (int p = 0; p < 4; ++p)
#pragma unroll
                for (int h = 0; h < 2; ++h) {
                    const unsigned* bb = &bl[p][2 * h];
                    int n = 2 * p + h;
                    mma16816(acc[0][n], ahf[0], bb);
                    mma16816(acc[1][n], ahf[1], bb);
                }
        }
    }

    // ---- store out[j,d] ----
#pragma unroll
    for (int f = 0; f < 2; ++f) {
        int jr = j0 + wm * 32 + f * 16 + (l >> 2);
        float* r0 = ob + (size_t)jr * DIM + wn * 64 + (l & 3) * 2;
#pragma unroll
        for (int n = 0; n < 8; ++n) {
            *(float2*)(r0 + n * 8)           = make_float2(acc[f][n][0], acc[f][n][1]);
            *(float2*)(r0 + n * 8 + 8 * DIM) = make_float2(acc[f][n][2], acc[f][n][3]);
        }
    }
}

// =====================================================================
extern "C" void kernel_launch(void* const* d_in, const int* in_sizes, int n_in,
                              void* d_out, int out_size) {
    const float* q = (const float*)d_in[0];
    // d_in[1] (k) unused by the reference
    const float* v = (const float*)d_in[2];

    float* out  = (float*)d_out;                      // [8,2048,128]
    float* attn = out + (size_t)BATCH * SEQ * DIM;    // [8,2048,2048]

    cudaFuncSetAttribute(pass1_kernel,
                         cudaFuncAttributeMaxDynamicSharedMemorySize, P1_SMEM);
    cudaFuncSetAttribute(pass2_kernel,
                         cudaFuncAttributeMaxDynamicSharedMemorySize, P2_SMEM);

    split_kernel<<<(BATCH * SEQ * DIM) / (256 * 4), 256>>>(q, v);

    dim3 g1(SEQ / 128, BATCH);
    pass1_kernel<<<g1, 256, P1_SMEM>>>(attn);

    dim3 g2(SEQ / 128, BATCH);
    pass2_kernel<<<g2, 256, P2_SMEM>>>(attn, out);
}